// round 1
// baseline (speedup 1.0000x reference)
#include <cuda_runtime.h>
#include <cuda_bf16.h>
#include <math.h>

#define BB 32
#define SS 512
#define TT 50
#define LL 562      // S+T
#define DD 512
#define HH 8
#define DHH 64
#define FFDIM 2048
#define NLAYER 4
#define VBB 30000
#define BLROWS (BB*LL)   // 17984
#define KSPLIT 75
#define KCHUNK 400       // 75*400 = 30000

// ---------------- scratch (device globals; no allocation allowed) ----------------
__device__ float g_wd[TT*VBB];                 // softmaxed word dist [50,30000]
__device__ float g_part[KSPLIT*TT*1024];       // split-K partials
__device__ float g_hmem[TT*1024];
__device__ float g_topic[TT*DD];
__device__ float g_q[BLROWS*DD];
__device__ float g_k[BLROWS*DD];
__device__ float g_v[BLROWS*DD];
__device__ float g_ctx[BLROWS*DD];
__device__ float g_t[BLROWS*DD];
__device__ float g_ff[(size_t)BLROWS*FFDIM];

// ---------------- helpers ----------------
__device__ __forceinline__ float warp_red_sum(float v){
    #pragma unroll
    for (int o=16;o>0;o>>=1) v += __shfl_xor_sync(0xffffffffu, v, o);
    return v;
}
__device__ __forceinline__ float warp_red_max(float v){
    #pragma unroll
    for (int o=16;o>0;o>>=1) v = fmaxf(v, __shfl_xor_sync(0xffffffffu, v, o));
    return v;
}

// ---------------- topic memory pipeline ----------------
// softmax over rows of (W_dec + b_dec): [50, 30000]
__global__ void k_wdec_softmax(const float* __restrict__ W, const float* __restrict__ bvec){
    int row = blockIdx.x, tid = threadIdx.x;
    __shared__ float red[8];
    const float* w = W + (size_t)row*VBB;
    float m = -1e30f;
    for (int i=tid;i<VBB;i+=256) m = fmaxf(m, w[i]+bvec[i]);
    m = warp_red_max(m);
    if ((tid&31)==0) red[tid>>5]=m;
    __syncthreads();
    float mm = red[0];
    #pragma unroll
    for (int i=1;i<8;i++) mm = fmaxf(mm, red[i]);
    float s = 0.f;
    for (int i=tid;i<VBB;i+=256) s += __expf(w[i]+bvec[i]-mm);
    s = warp_red_sum(s);
    __syncthreads();
    if ((tid&31)==0) red[tid>>5]=s;
    __syncthreads();
    float ss = 0.f;
    #pragma unroll
    for (int i=0;i<8;i++) ss += red[i];
    float inv = 1.0f/ss;
    for (int i=tid;i<VBB;i+=256) g_wd[(size_t)row*VBB+i] = __expf(w[i]+bvec[i]-mm)*inv;
}

// word_dist[50,30000] @ mem_W1[30000,1024] — split-K, deterministic partial buffer
__global__ void k_mem_gemm1(const float* __restrict__ W1){
    __shared__ float wds[16][52];
    __shared__ float Ws[16][128];
    int n0 = blockIdx.x*128;
    int k0 = blockIdx.y*KCHUNK;
    int tid = threadIdx.x;
    int n = tid & 127, mb = (tid>>7)*25;
    float acc[25];
    #pragma unroll
    for (int i=0;i<25;i++) acc[i]=0.f;
    for (int kt=0; kt<KCHUNK; kt+=16){
        int kb = k0+kt;
        for (int x=tid;x<800;x+=256){ int m=x>>4, kk=x&15; wds[kk][m]=g_wd[(size_t)m*VBB + kb + kk]; }
        #pragma unroll
        for (int jj=0;jj<2;jj++){
            int idx = tid + jj*256;
            int r = idx>>5, c4 = (idx&31)*4;
            *(float4*)&Ws[r][c4] = *(const float4*)(W1 + (size_t)(kb+r)*1024 + n0 + c4);
        }
        __syncthreads();
        #pragma unroll
        for (int kk=0;kk<16;kk++){
            float w = Ws[kk][n];
            #pragma unroll
            for (int i=0;i<25;i++) acc[i] += wds[kk][mb+i]*w;
        }
        __syncthreads();
    }
    float* out = g_part + (size_t)blockIdx.y*(TT*1024);
    #pragma unroll
    for (int i=0;i<25;i++) out[(mb+i)*1024 + n0 + n] = acc[i];
}

__global__ void k_mem_reduce(const float* __restrict__ b1){
    int i = blockIdx.x*256 + threadIdx.x;
    if (i >= TT*1024) return;
    float s = 0.f;
    for (int ks=0; ks<KSPLIT; ks++) s += g_part[(size_t)ks*(TT*1024) + i];
    s += b1[i & 1023];
    g_hmem[i] = fmaxf(s, 0.f);
}

// hmem[50,1024] @ mem_W2[1024,512] + b2 -> LN -> topic_memory [50,512]
__global__ void k_mem2_ln(const float* __restrict__ W2, const float* __restrict__ b2,
                          const float* __restrict__ gg, const float* __restrict__ bbv){
    __shared__ float sh[1024];
    __shared__ float red[8];
    int row = blockIdx.x, tid = threadIdx.x;
    for (int i=tid;i<1024;i+=256) sh[i]=g_hmem[row*1024+i];
    __syncthreads();
    float a0=0.f, a1=0.f;
    #pragma unroll 4
    for (int k=0;k<1024;k++){
        float h = sh[k];
        a0 = fmaf(h, W2[(size_t)k*512+tid], a0);
        a1 = fmaf(h, W2[(size_t)k*512+256+tid], a1);
    }
    a0 += b2[tid]; a1 += b2[256+tid];
    float s = a0+a1;
    s = warp_red_sum(s);
    if ((tid&31)==0) red[tid>>5]=s;
    __syncthreads();
    float tot=0.f;
    #pragma unroll
    for (int i=0;i<8;i++) tot+=red[i];
    float mean = tot*(1.f/512.f);
    float d0=a0-mean, d1=a1-mean;
    float q = d0*d0+d1*d1;
    q = warp_red_sum(q);
    __syncthreads();
    if ((tid&31)==0) red[tid>>5]=q;
    __syncthreads();
    float vq=0.f;
    #pragma unroll
    for (int i=0;i<8;i++) vq+=red[i];
    float inv = rsqrtf(vq*(1.f/512.f) + 1e-12f);
    g_topic[row*512+tid]     = d0*inv*gg[tid]     + bbv[tid];
    g_topic[row*512+256+tid] = d1*inv*gg[256+tid] + bbv[256+tid];
}

// build hidden [B, L, D] into d_out: [real tokens | memory | padding-gather]
__global__ void k_build_hidden(const int* __restrict__ ids, const int* __restrict__ lens_p,
                               const float* __restrict__ embed, float* __restrict__ hid){
    int r = blockIdx.x;
    int b = r / LL, j = r % LL;
    int len = lens_p[b]; len = min(max(len,1),SS);
    const float* src;
    if (j >= len && j < len+TT){
        src = g_topic + (size_t)(j-len)*DD;
    } else {
        int sj = (j < len) ? j : (j - TT);
        sj = min(max(sj,0), SS-1);
        src = embed + (size_t)ids[b*SS + sj]*DD;
    }
    const float4* s4 = (const float4*)src;
    float4* dst = (float4*)(hid + (size_t)r*DD);
    dst[threadIdx.x] = s4[threadIdx.x];   // 128 threads * float4 = 512 floats
}

// ---------------- generic fp32 tiled GEMM: C[M,N] = A[M,K] @ W[K,N] + bias (+act) ----------------
template<int ACT>
__global__ __launch_bounds__(256)
void k_gemm(const float* __restrict__ A, const float* __restrict__ W,
            const float* __restrict__ bias, float* __restrict__ C,
            int M, int N, int K)
{
    __shared__ float As[16][132];
    __shared__ float Ws[16][128];
    int m0 = blockIdx.x*128, n0 = blockIdx.y*128;
    int tid = threadIdx.x, tx = tid&15, ty = tid>>4;
    float acc[8][8];
    #pragma unroll
    for (int i=0;i<8;i++)
        #pragma unroll
        for (int j=0;j<8;j++) acc[i][j]=0.f;

    for (int k0=0;k0<K;k0+=16){
        #pragma unroll
        for (int jj=0;jj<2;jj++){
            int idx = tid*2+jj;
            int r = idx>>2, c4 = (idx&3)*4;
            float4 av = make_float4(0.f,0.f,0.f,0.f);
            int gr = m0+r;
            if (gr < M) av = *(const float4*)(A + (size_t)gr*K + k0 + c4);
            As[c4+0][r]=av.x; As[c4+1][r]=av.y; As[c4+2][r]=av.z; As[c4+3][r]=av.w;
        }
        #pragma unroll
        for (int jj=0;jj<2;jj++){
            int idx = tid + jj*256;
            int r = idx>>5, c4 = (idx&31)*4;
            *(float4*)&Ws[r][c4] = *(const float4*)(W + (size_t)(k0+r)*N + n0 + c4);
        }
        __syncthreads();
        #pragma unroll
        for (int k=0;k<16;k++){
            float4 a0 = *(const float4*)&As[k][ty*8];
            float4 a1 = *(const float4*)&As[k][ty*8+4];
            float4 b0 = *(const float4*)&Ws[k][tx*8];
            float4 b1 = *(const float4*)&Ws[k][tx*8+4];
            float a[8] = {a0.x,a0.y,a0.z,a0.w,a1.x,a1.y,a1.z,a1.w};
            float b[8] = {b0.x,b0.y,b0.z,b0.w,b1.x,b1.y,b1.z,b1.w};
            #pragma unroll
            for (int i=0;i<8;i++)
                #pragma unroll
                for (int j=0;j<8;j++) acc[i][j] = fmaf(a[i], b[j], acc[i][j]);
        }
        __syncthreads();
    }
    float bv[8];
    #pragma unroll
    for (int j=0;j<8;j++) bv[j] = bias[n0+tx*8+j];
    #pragma unroll
    for (int i=0;i<8;i++){
        int gr = m0+ty*8+i;
        if (gr >= M) continue;
        float* crow = C + (size_t)gr*N + n0 + tx*8;
        #pragma unroll
        for (int j=0;j<8;j++){
            float v = acc[i][j] + bv[j];
            if (ACT==1) v = 0.5f*v*(1.0f+erff(v*0.70710678118654752f)); // exact gelu
            crow[j] = v;
        }
    }
}

// ---------------- fused flash attention (fp32, online softmax) ----------------
// grid: (ceil(L/64), B*H); block 256 (16x16); Q-tile 64 rows, KV-tile 32
__global__ __launch_bounds__(256)
void k_attn(const int* __restrict__ lens_p, float* __restrict__ O){
    __shared__ float Qst[64][68];  // [k][r]  transposed
    __shared__ float Kst[64][36];  // [k][c]  transposed
    __shared__ float Vs [32][68];  // [c][d]
    __shared__ float Ps [64][36];  // [r][c]
    int bh = blockIdx.y;
    int b = bh / HH, h = bh % HH;
    int q0 = blockIdx.x*64;
    int tid = threadIdx.x, tx = tid&15, ty = tid>>4;
    int len = lens_p[b]; len = min(max(len,1),SS);
    int valid = len + TT;

    // load Q tile transposed: Qst[d][r]
    for (int x=tid; x<1024; x+=256){
        int r = x>>4, c4 = (x&15)*4;
        int gr = q0+r;
        float4 v = make_float4(0.f,0.f,0.f,0.f);
        if (gr < LL) v = *(const float4*)(g_q + (size_t)(b*LL+gr)*DD + h*64 + c4);
        Qst[c4+0][r]=v.x; Qst[c4+1][r]=v.y; Qst[c4+2][r]=v.z; Qst[c4+3][r]=v.w;
    }
    float m_i[4], l_i[4], acc[4][4];
    #pragma unroll
    for (int i=0;i<4;i++){ m_i[i]=-1e30f; l_i[i]=0.f;
        #pragma unroll
        for (int j=0;j<4;j++) acc[i][j]=0.f; }
    __syncthreads();

    const int nkt = (LL+31)/32;  // 18
    for (int kt=0; kt<nkt; kt++){
        int k0 = kt*32;
        for (int x=tid; x<512; x+=256){
            int r = x>>4, c4 = (x&15)*4;
            int gr = k0+r;
            float4 kv = make_float4(0.f,0.f,0.f,0.f);
            float4 vv = make_float4(0.f,0.f,0.f,0.f);
            if (gr < LL){
                kv = *(const float4*)(g_k + (size_t)(b*LL+gr)*DD + h*64 + c4);
                vv = *(const float4*)(g_v + (size_t)(b*LL+gr)*DD + h*64 + c4);
            }
            Kst[c4+0][r]=kv.x; Kst[c4+1][r]=kv.y; Kst[c4+2][r]=kv.z; Kst[c4+3][r]=kv.w;
            *(float4*)&Vs[r][c4] = vv;
        }
        __syncthreads();

        // scores: s[i][j] for rows ty*4+i, cols tx*2+j
        float s[4][2];
        #pragma unroll
        for (int i=0;i<4;i++){ s[i][0]=0.f; s[i][1]=0.f; }
        #pragma unroll 8
        for (int k=0;k<64;k++){
            float4 qv = *(const float4*)&Qst[k][ty*4];
            float2 kv = *(const float2*)&Kst[k][tx*2];
            s[0][0]=fmaf(qv.x,kv.x,s[0][0]); s[0][1]=fmaf(qv.x,kv.y,s[0][1]);
            s[1][0]=fmaf(qv.y,kv.x,s[1][0]); s[1][1]=fmaf(qv.y,kv.y,s[1][1]);
            s[2][0]=fmaf(qv.z,kv.x,s[2][0]); s[2][1]=fmaf(qv.z,kv.y,s[2][1]);
            s[3][0]=fmaf(qv.w,kv.x,s[3][0]); s[3][1]=fmaf(qv.w,kv.y,s[3][1]);
        }
        #pragma unroll
        for (int j=0;j<2;j++){
            float msk = (k0 + tx*2 + j >= valid) ? -10000.0f : 0.0f;
            #pragma unroll
            for (int i=0;i<4;i++) s[i][j] = s[i][j]*0.125f + msk;
        }
        // online softmax update per row (reduce over 16 tx lanes)
        #pragma unroll
        for (int i=0;i<4;i++){
            float mv = fmaxf(s[i][0], s[i][1]);
            #pragma unroll
            for (int o=8;o>0;o>>=1) mv = fmaxf(mv, __shfl_xor_sync(0xffffffffu, mv, o));
            float mnew = fmaxf(m_i[i], mv);
            float alpha = __expf(m_i[i]-mnew);
            float p0 = __expf(s[i][0]-mnew), p1 = __expf(s[i][1]-mnew);
            float ssum = p0+p1;
            #pragma unroll
            for (int o=8;o>0;o>>=1) ssum += __shfl_xor_sync(0xffffffffu, ssum, o);
            l_i[i] = l_i[i]*alpha + ssum;
            m_i[i] = mnew;
            #pragma unroll
            for (int j=0;j<4;j++) acc[i][j] *= alpha;
            Ps[ty*4+i][tx*2+0] = p0;
            Ps[ty*4+i][tx*2+1] = p1;
        }
        __syncthreads();
        // O += P @ V
        #pragma unroll 8
        for (int c=0;c<32;c++){
            float4 vv = *(const float4*)&Vs[c][tx*4];
            float p0=Ps[ty*4+0][c], p1=Ps[ty*4+1][c], p2=Ps[ty*4+2][c], p3=Ps[ty*4+3][c];
            acc[0][0]=fmaf(p0,vv.x,acc[0][0]); acc[0][1]=fmaf(p0,vv.y,acc[0][1]); acc[0][2]=fmaf(p0,vv.z,acc[0][2]); acc[0][3]=fmaf(p0,vv.w,acc[0][3]);
            acc[1][0]=fmaf(p1,vv.x,acc[1][0]); acc[1][1]=fmaf(p1,vv.y,acc[1][1]); acc[1][2]=fmaf(p1,vv.z,acc[1][2]); acc[1][3]=fmaf(p1,vv.w,acc[1][3]);
            acc[2][0]=fmaf(p2,vv.x,acc[2][0]); acc[2][1]=fmaf(p2,vv.y,acc[2][1]); acc[2][2]=fmaf(p2,vv.z,acc[2][2]); acc[2][3]=fmaf(p2,vv.w,acc[2][3]);
            acc[3][0]=fmaf(p3,vv.x,acc[3][0]); acc[3][1]=fmaf(p3,vv.y,acc[3][1]); acc[3][2]=fmaf(p3,vv.z,acc[3][2]); acc[3][3]=fmaf(p3,vv.w,acc[3][3]);
        }
        __syncthreads();
    }
    // write out
    #pragma unroll
    for (int i=0;i<4;i++){
        int gr = q0 + ty*4 + i;
        if (gr < LL){
            float inv = 1.0f/l_i[i];
            float4 o;
            o.x=acc[i][0]*inv; o.y=acc[i][1]*inv; o.z=acc[i][2]*inv; o.w=acc[i][3]*inv;
            *(float4*)(O + (size_t)(b*LL+gr)*DD + h*64 + tx*4) = o;
        }
    }
}

// ---------------- residual + LayerNorm (in place on hidden) ----------------
__global__ void k_addln(float* __restrict__ hid, const float* __restrict__ t,
                        const float* __restrict__ gg, const float* __restrict__ bbv){
    __shared__ float red[4];
    int r = blockIdx.x, tid = threadIdx.x;
    float4 a = *(float4*)(hid + (size_t)r*DD + tid*4);
    float4 c = *(const float4*)(t + (size_t)r*DD + tid*4);
    float x0=a.x+c.x, x1=a.y+c.y, x2=a.z+c.z, x3=a.w+c.w;
    float s = x0+x1+x2+x3;
    s = warp_red_sum(s);
    if ((tid&31)==0) red[tid>>5]=s;
    __syncthreads();
    float mean = (red[0]+red[1]+red[2]+red[3])*(1.f/512.f);
    float d0=x0-mean, d1=x1-mean, d2=x2-mean, d3=x3-mean;
    float q = d0*d0+d1*d1+d2*d2+d3*d3;
    q = warp_red_sum(q);
    __syncthreads();
    if ((tid&31)==0) red[tid>>5]=q;
    __syncthreads();
    float var = (red[0]+red[1]+red[2]+red[3])*(1.f/512.f);
    float inv = rsqrtf(var + 1e-12f);
    float4 gv = *(const float4*)(gg + tid*4);
    float4 bv = *(const float4*)(bbv + tid*4);
    float4 o;
    o.x = d0*inv*gv.x + bv.x;
    o.y = d1*inv*gv.y + bv.y;
    o.z = d2*inv*gv.z + bv.z;
    o.w = d3*inv*gv.w + bv.w;
    *(float4*)(hid + (size_t)r*DD + tid*4) = o;
}

// ---------------- host ----------------
extern "C" void kernel_launch(void* const* d_in, const int* in_sizes, int n_in,
                              void* d_out, int out_size) {
    const int*   input_ids = (const int*)  d_in[0];
    const int*   seq_lens  = (const int*)  d_in[1];
    const float* embed     = (const float*)d_in[2];
    const float* W_dec     = (const float*)d_in[3];
    const float* b_dec     = (const float*)d_in[4];
    const float* mem_W1    = (const float*)d_in[5];
    const float* mem_b1    = (const float*)d_in[6];
    const float* mem_W2    = (const float*)d_in[7];
    const float* mem_b2    = (const float*)d_in[8];
    const float* mem_ln_g  = (const float*)d_in[9];
    const float* mem_ln_b  = (const float*)d_in[10];
    const float* Wq = (const float*)d_in[11];
    const float* bq = (const float*)d_in[12];
    const float* Wk = (const float*)d_in[13];
    const float* bk = (const float*)d_in[14];
    const float* Wv = (const float*)d_in[15];
    const float* bv = (const float*)d_in[16];
    const float* Wo = (const float*)d_in[17];
    const float* bo = (const float*)d_in[18];
    const float* ln1_g = (const float*)d_in[19];
    const float* ln1_b = (const float*)d_in[20];
    const float* Wi = (const float*)d_in[21];
    const float* bi = (const float*)d_in[22];
    const float* Wf = (const float*)d_in[23];
    const float* bf = (const float*)d_in[24];
    const float* ln2_g = (const float*)d_in[25];
    const float* ln2_b = (const float*)d_in[26];

    float* hidden = (float*)d_out;

    float *p_q, *p_k, *p_v, *p_ctx, *p_t, *p_ff;
    cudaGetSymbolAddress((void**)&p_q,   g_q);
    cudaGetSymbolAddress((void**)&p_k,   g_k);
    cudaGetSymbolAddress((void**)&p_v,   g_v);
    cudaGetSymbolAddress((void**)&p_ctx, g_ctx);
    cudaGetSymbolAddress((void**)&p_t,   g_t);
    cudaGetSymbolAddress((void**)&p_ff,  g_ff);

    // topic memory
    k_wdec_softmax<<<TT, 256>>>(W_dec, b_dec);
    k_mem_gemm1<<<dim3(8, KSPLIT), 256>>>(mem_W1);
    k_mem_reduce<<<(TT*1024+255)/256, 256>>>(mem_b1);
    k_mem2_ln<<<TT, 256>>>(mem_W2, mem_b2, mem_ln_g, mem_ln_b);

    // build hidden into d_out
    k_build_hidden<<<BLROWS, 128>>>(input_ids, seq_lens, embed, hidden);

    const int MB = (BLROWS + 127)/128;  // 141
    for (int l = 0; l < NLAYER; l++) {
        const float* wq = Wq + (size_t)l*DD*DD;
        const float* wk = Wk + (size_t)l*DD*DD;
        const float* wv = Wv + (size_t)l*DD*DD;
        const float* wo = Wo + (size_t)l*DD*DD;
        const float* wi = Wi + (size_t)l*DD*FFDIM;
        const float* wf = Wf + (size_t)l*FFDIM*DD;

        k_gemm<0><<<dim3(MB, DD/128), 256>>>(hidden, wq, bq + l*DD, p_q, BLROWS, DD, DD);
        k_gemm<0><<<dim3(MB, DD/128), 256>>>(hidden, wk, bk + l*DD, p_k, BLROWS, DD, DD);
        k_gemm<0><<<dim3(MB, DD/128), 256>>>(hidden, wv, bv + l*DD, p_v, BLROWS, DD, DD);

        k_attn<<<dim3((LL+63)/64, BB*HH), 256>>>(seq_lens, p_ctx);

        k_gemm<0><<<dim3(MB, DD/128), 256>>>(p_ctx, wo, bo + l*DD, p_t, BLROWS, DD, DD);
        k_addln<<<BLROWS, 128>>>(hidden, p_t, ln1_g + l*DD, ln1_b + l*DD);

        k_gemm<1><<<dim3(MB, FFDIM/128), 256>>>(hidden, wi, bi + l*FFDIM, p_ff, BLROWS, FFDIM, DD);
        k_gemm<0><<<dim3(MB, DD/128), 256>>>(p_ff, wf, bf + l*DD, p_t, BLROWS, DD, FFDIM);
        k_addln<<<BLROWS, 128>>>(hidden, p_t, ln2_g + l*DD, ln2_b + l*DD);
    }
}

// round 2
// speedup vs baseline: 2.0763x; 2.0763x over previous
#include <cuda_runtime.h>
#include <cuda_bf16.h>
#include <math.h>

#define BB 32
#define SS 512
#define TT 50
#define LL 562      // S+T
#define DD 512
#define HH 8
#define DHH 64
#define FFDIM 2048
#define NLAYER 4
#define VBB 30000
#define BLROWS (BB*LL)   // 17984
#define KSPLIT 75
#define KCHUNK 400       // 75*400 = 30000

// ---------------- scratch (device globals; no allocation allowed) ----------------
__device__ float g_wd[TT*VBB];                 // softmaxed word dist [50,30000]
__device__ float g_part[KSPLIT*TT*1024];       // split-K partials
__device__ float g_hmem[TT*1024];
__device__ float g_topic[TT*DD];
__device__ float g_q[BLROWS*DD];
__device__ float g_k[BLROWS*DD];
__device__ float g_v[BLROWS*DD];
__device__ float g_ctx[BLROWS*DD];
__device__ float g_t[BLROWS*DD];
__device__ float g_ff[(size_t)BLROWS*FFDIM];

// ---------------- helpers ----------------
__device__ __forceinline__ float warp_red_sum(float v){
    #pragma unroll
    for (int o=16;o>0;o>>=1) v += __shfl_xor_sync(0xffffffffu, v, o);
    return v;
}
__device__ __forceinline__ float warp_red_max(float v){
    #pragma unroll
    for (int o=16;o>0;o>>=1) v = fmaxf(v, __shfl_xor_sync(0xffffffffu, v, o));
    return v;
}
__device__ __forceinline__ unsigned f2tf32(float x){
    unsigned r;
    asm("cvt.rna.tf32.f32 %0, %1;" : "=r"(r) : "f"(x));
    return r;
}

// ---------------- topic memory pipeline ----------------
__global__ void k_wdec_softmax(const float* __restrict__ W, const float* __restrict__ bvec){
    int row = blockIdx.x, tid = threadIdx.x;
    __shared__ float red[8];
    const float* w = W + (size_t)row*VBB;
    float m = -1e30f;
    for (int i=tid;i<VBB;i+=256) m = fmaxf(m, w[i]+bvec[i]);
    m = warp_red_max(m);
    if ((tid&31)==0) red[tid>>5]=m;
    __syncthreads();
    float mm = red[0];
    #pragma unroll
    for (int i=1;i<8;i++) mm = fmaxf(mm, red[i]);
    float s = 0.f;
    for (int i=tid;i<VBB;i+=256) s += __expf(w[i]+bvec[i]-mm);
    s = warp_red_sum(s);
    __syncthreads();
    if ((tid&31)==0) red[tid>>5]=s;
    __syncthreads();
    float ss = 0.f;
    #pragma unroll
    for (int i=0;i<8;i++) ss += red[i];
    float inv = 1.0f/ss;
    for (int i=tid;i<VBB;i+=256) g_wd[(size_t)row*VBB+i] = __expf(w[i]+bvec[i]-mm)*inv;
}

__global__ void k_mem_gemm1(const float* __restrict__ W1){
    __shared__ float wds[16][52];
    __shared__ float Ws[16][128];
    int n0 = blockIdx.x*128;
    int k0 = blockIdx.y*KCHUNK;
    int tid = threadIdx.x;
    int n = tid & 127, mb = (tid>>7)*25;
    float acc[25];
    #pragma unroll
    for (int i=0;i<25;i++) acc[i]=0.f;
    for (int kt=0; kt<KCHUNK; kt+=16){
        int kb = k0+kt;
        for (int x=tid;x<800;x+=256){ int m=x>>4, kk=x&15; wds[kk][m]=g_wd[(size_t)m*VBB + kb + kk]; }
        #pragma unroll
        for (int jj=0;jj<2;jj++){
            int idx = tid + jj*256;
            int r = idx>>5, c4 = (idx&31)*4;
            *(float4*)&Ws[r][c4] = *(const float4*)(W1 + (size_t)(kb+r)*1024 + n0 + c4);
        }
        __syncthreads();
        #pragma unroll
        for (int kk=0;kk<16;kk++){
            float w = Ws[kk][n];
            #pragma unroll
            for (int i=0;i<25;i++) acc[i] += wds[kk][mb+i]*w;
        }
        __syncthreads();
    }
    float* out = g_part + (size_t)blockIdx.y*(TT*1024);
    #pragma unroll
    for (int i=0;i<25;i++) out[(mb+i)*1024 + n0 + n] = acc[i];
}

__global__ void k_mem_reduce(const float* __restrict__ b1){
    int i = blockIdx.x*256 + threadIdx.x;
    if (i >= TT*1024) return;
    float s = 0.f;
    for (int ks=0; ks<KSPLIT; ks++) s += g_part[(size_t)ks*(TT*1024) + i];
    s += b1[i & 1023];
    g_hmem[i] = fmaxf(s, 0.f);
}

__global__ void k_mem2_ln(const float* __restrict__ W2, const float* __restrict__ b2,
                          const float* __restrict__ gg, const float* __restrict__ bbv){
    __shared__ float sh[1024];
    __shared__ float red[8];
    int row = blockIdx.x, tid = threadIdx.x;
    for (int i=tid;i<1024;i+=256) sh[i]=g_hmem[row*1024+i];
    __syncthreads();
    float a0=0.f, a1=0.f;
    #pragma unroll 4
    for (int k=0;k<1024;k++){
        float h = sh[k];
        a0 = fmaf(h, W2[(size_t)k*512+tid], a0);
        a1 = fmaf(h, W2[(size_t)k*512+256+tid], a1);
    }
    a0 += b2[tid]; a1 += b2[256+tid];
    float s = a0+a1;
    s = warp_red_sum(s);
    if ((tid&31)==0) red[tid>>5]=s;
    __syncthreads();
    float tot=0.f;
    #pragma unroll
    for (int i=0;i<8;i++) tot+=red[i];
    float mean = tot*(1.f/512.f);
    float d0=a0-mean, d1=a1-mean;
    float q = d0*d0+d1*d1;
    q = warp_red_sum(q);
    __syncthreads();
    if ((tid&31)==0) red[tid>>5]=q;
    __syncthreads();
    float vq=0.f;
    #pragma unroll
    for (int i=0;i<8;i++) vq+=red[i];
    float inv = rsqrtf(vq*(1.f/512.f) + 1e-12f);
    g_topic[row*512+tid]     = d0*inv*gg[tid]     + bbv[tid];
    g_topic[row*512+256+tid] = d1*inv*gg[256+tid] + bbv[256+tid];
}

__global__ void k_build_hidden(const int* __restrict__ ids, const int* __restrict__ lens_p,
                               const float* __restrict__ embed, float* __restrict__ hid){
    int r = blockIdx.x;
    int b = r / LL, j = r % LL;
    int len = lens_p[b]; len = min(max(len,1),SS);
    const float* src;
    if (j >= len && j < len+TT){
        src = g_topic + (size_t)(j-len)*DD;
    } else {
        int sj = (j < len) ? j : (j - TT);
        sj = min(max(sj,0), SS-1);
        src = embed + (size_t)ids[b*SS + sj]*DD;
    }
    const float4* s4 = (const float4*)src;
    float4* dst = (float4*)(hid + (size_t)r*DD);
    dst[threadIdx.x] = s4[threadIdx.x];
}

// ---------------- TF32 tensor-core GEMM: C[M,N] = A[M,K] @ W[K,N] + bias (+act) ----------
// 128x128 block tile, kTile=32, 8 warps of 64x32 (2x4 warp grid), mma.m16n8k8.tf32
template<int ACT>
__global__ __launch_bounds__(256)
void k_gemm_mma(const float* __restrict__ A, const float* __restrict__ W,
                const float* __restrict__ bias, float* __restrict__ C,
                int M, int N, int K)
{
    __shared__ float As[128][36];   // [m][k], stride 36: frag bank = (4m+k)%32 conflict-free
    __shared__ float Ws[32][136];   // [k][n], stride 136: frag bank = (8q+g)%32 conflict-free
    const int tid = threadIdx.x;
    const int lane = tid & 31, warp = tid >> 5;
    const int wm = warp >> 2, wn = warp & 3;        // 2 x 4 warps
    const int m0 = blockIdx.x*128, n0 = blockIdx.y*128;
    const int q = lane & 3, g = lane >> 2;

    float acc[4][4][4];
    #pragma unroll
    for (int a=0;a<4;a++)
        #pragma unroll
        for (int b=0;b<4;b++)
            #pragma unroll
            for (int c=0;c<4;c++) acc[a][b][c]=0.f;

    for (int k0 = 0; k0 < K; k0 += 32){
        __syncthreads();
        // load A tile -> As[m][k] (tf32-rounded)
        #pragma unroll
        for (int i=0;i<4;i++){
            int s = tid + i*256;
            int m = s>>3, kv = s&7;
            int gr = m0+m;
            float4 v = make_float4(0.f,0.f,0.f,0.f);
            if (gr < M) v = *(const float4*)(A + (size_t)gr*K + k0 + kv*4);
            uint4 t;
            t.x = f2tf32(v.x); t.y = f2tf32(v.y); t.z = f2tf32(v.z); t.w = f2tf32(v.w);
            *(uint4*)&As[m][kv*4] = t;
        }
        // load W tile -> Ws[k][n]
        #pragma unroll
        for (int i=0;i<4;i++){
            int s = tid + i*256;
            int kk = s>>5, nv = s&31;
            float4 v = *(const float4*)(W + (size_t)(k0+kk)*N + n0 + nv*4);
            uint4 t;
            t.x = f2tf32(v.x); t.y = f2tf32(v.y); t.z = f2tf32(v.z); t.w = f2tf32(v.w);
            *(uint4*)&Ws[kk][nv*4] = t;
        }
        __syncthreads();

        #pragma unroll
        for (int k8=0;k8<32;k8+=8){
            unsigned af[4][4], bf[4][2];
            #pragma unroll
            for (int mi=0;mi<4;mi++){
                int mr = wm*64 + mi*16 + g;
                af[mi][0] = __float_as_uint(As[mr  ][k8+q  ]);
                af[mi][1] = __float_as_uint(As[mr+8][k8+q  ]);
                af[mi][2] = __float_as_uint(As[mr  ][k8+q+4]);
                af[mi][3] = __float_as_uint(As[mr+8][k8+q+4]);
            }
            #pragma unroll
            for (int nj=0;nj<4;nj++){
                int nc = wn*32 + nj*8 + g;
                bf[nj][0] = __float_as_uint(Ws[k8+q  ][nc]);
                bf[nj][1] = __float_as_uint(Ws[k8+q+4][nc]);
            }
            #pragma unroll
            for (int mi=0;mi<4;mi++)
                #pragma unroll
                for (int nj=0;nj<4;nj++){
                    asm volatile(
                        "mma.sync.aligned.m16n8k8.row.col.f32.tf32.tf32.f32 "
                        "{%0,%1,%2,%3}, {%4,%5,%6,%7}, {%8,%9}, {%0,%1,%2,%3};"
                        : "+f"(acc[mi][nj][0]), "+f"(acc[mi][nj][1]),
                          "+f"(acc[mi][nj][2]), "+f"(acc[mi][nj][3])
                        : "r"(af[mi][0]), "r"(af[mi][1]), "r"(af[mi][2]), "r"(af[mi][3]),
                          "r"(bf[nj][0]), "r"(bf[nj][1]));
                }
        }
    }

    // epilogue: c0:(g, 2q) c1:(g, 2q+1) c2:(g+8, 2q) c3:(g+8, 2q+1) per 16x8 tile
    #pragma unroll
    for (int nj=0;nj<4;nj++){
        int c0 = n0 + wn*32 + nj*8 + q*2;
        float bv0 = bias[c0], bv1 = bias[c0+1];
        #pragma unroll
        for (int mi=0;mi<4;mi++){
            int r0 = m0 + wm*64 + mi*16 + g;
            float v0 = acc[mi][nj][0] + bv0;
            float v1 = acc[mi][nj][1] + bv1;
            float v2 = acc[mi][nj][2] + bv0;
            float v3 = acc[mi][nj][3] + bv1;
            if (ACT==1){
                v0 = 0.5f*v0*(1.0f+erff(v0*0.70710678118654752f));
                v1 = 0.5f*v1*(1.0f+erff(v1*0.70710678118654752f));
                v2 = 0.5f*v2*(1.0f+erff(v2*0.70710678118654752f));
                v3 = 0.5f*v3*(1.0f+erff(v3*0.70710678118654752f));
            }
            if (r0 < M)   { float2 o = make_float2(v0,v1); *(float2*)(C + (size_t)r0*N + c0) = o; }
            if (r0+8 < M) { float2 o = make_float2(v2,v3); *(float2*)(C + (size_t)(r0+8)*N + c0) = o; }
        }
    }
}

// ---------------- fused flash attention (fp32, online softmax) ----------------
__global__ __launch_bounds__(256)
void k_attn(const int* __restrict__ lens_p, float* __restrict__ O){
    __shared__ float Qst[64][68];
    __shared__ float Kst[64][36];
    __shared__ float Vs [32][68];
    __shared__ float Ps [64][36];
    int bh = blockIdx.y;
    int b = bh / HH, h = bh % HH;
    int q0 = blockIdx.x*64;
    int tid = threadIdx.x, tx = tid&15, ty = tid>>4;
    int len = lens_p[b]; len = min(max(len,1),SS);
    int valid = len + TT;

    for (int x=tid; x<1024; x+=256){
        int r = x>>4, c4 = (x&15)*4;
        int gr = q0+r;
        float4 v = make_float4(0.f,0.f,0.f,0.f);
        if (gr < LL) v = *(const float4*)(g_q + (size_t)(b*LL+gr)*DD + h*64 + c4);
        Qst[c4+0][r]=v.x; Qst[c4+1][r]=v.y; Qst[c4+2][r]=v.z; Qst[c4+3][r]=v.w;
    }
    float m_i[4], l_i[4], acc[4][4];
    #pragma unroll
    for (int i=0;i<4;i++){ m_i[i]=-1e30f; l_i[i]=0.f;
        #pragma unroll
        for (int j=0;j<4;j++) acc[i][j]=0.f; }
    __syncthreads();

    const int nkt = (LL+31)/32;
    for (int kt=0; kt<nkt; kt++){
        int k0 = kt*32;
        for (int x=tid; x<512; x+=256){
            int r = x>>4, c4 = (x&15)*4;
            int gr = k0+r;
            float4 kv = make_float4(0.f,0.f,0.f,0.f);
            float4 vv = make_float4(0.f,0.f,0.f,0.f);
            if (gr < LL){
                kv = *(const float4*)(g_k + (size_t)(b*LL+gr)*DD + h*64 + c4);
                vv = *(const float4*)(g_v + (size_t)(b*LL+gr)*DD + h*64 + c4);
            }
            Kst[c4+0][r]=kv.x; Kst[c4+1][r]=kv.y; Kst[c4+2][r]=kv.z; Kst[c4+3][r]=kv.w;
            *(float4*)&Vs[r][c4] = vv;
        }
        __syncthreads();

        float s[4][2];
        #pragma unroll
        for (int i=0;i<4;i++){ s[i][0]=0.f; s[i][1]=0.f; }
        #pragma unroll 8
        for (int k=0;k<64;k++){
            float4 qv = *(const float4*)&Qst[k][ty*4];
            float2 kv = *(const float2*)&Kst[k][tx*2];
            s[0][0]=fmaf(qv.x,kv.x,s[0][0]); s[0][1]=fmaf(qv.x,kv.y,s[0][1]);
            s[1][0]=fmaf(qv.y,kv.x,s[1][0]); s[1][1]=fmaf(qv.y,kv.y,s[1][1]);
            s[2][0]=fmaf(qv.z,kv.x,s[2][0]); s[2][1]=fmaf(qv.z,kv.y,s[2][1]);
            s[3][0]=fmaf(qv.w,kv.x,s[3][0]); s[3][1]=fmaf(qv.w,kv.y,s[3][1]);
        }
        #pragma unroll
        for (int j=0;j<2;j++){
            float msk = (k0 + tx*2 + j >= valid) ? -10000.0f : 0.0f;
            #pragma unroll
            for (int i=0;i<4;i++) s[i][j] = s[i][j]*0.125f + msk;
        }
        #pragma unroll
        for (int i=0;i<4;i++){
            float mv = fmaxf(s[i][0], s[i][1]);
            #pragma unroll
            for (int o=8;o>0;o>>=1) mv = fmaxf(mv, __shfl_xor_sync(0xffffffffu, mv, o));
            float mnew = fmaxf(m_i[i], mv);
            float alpha = __expf(m_i[i]-mnew);
            float p0 = __expf(s[i][0]-mnew), p1 = __expf(s[i][1]-mnew);
            float ssum = p0+p1;
            #pragma unroll
            for (int o=8;o>0;o>>=1) ssum += __shfl_xor_sync(0xffffffffu, ssum, o);
            l_i[i] = l_i[i]*alpha + ssum;
            m_i[i] = mnew;
            #pragma unroll
            for (int j=0;j<4;j++) acc[i][j] *= alpha;
            Ps[ty*4+i][tx*2+0] = p0;
            Ps[ty*4+i][tx*2+1] = p1;
        }
        __syncthreads();
        #pragma unroll 8
        for (int c=0;c<32;c++){
            float4 vv = *(const float4*)&Vs[c][tx*4];
            float p0=Ps[ty*4+0][c], p1=Ps[ty*4+1][c], p2=Ps[ty*4+2][c], p3=Ps[ty*4+3][c];
            acc[0][0]=fmaf(p0,vv.x,acc[0][0]); acc[0][1]=fmaf(p0,vv.y,acc[0][1]); acc[0][2]=fmaf(p0,vv.z,acc[0][2]); acc[0][3]=fmaf(p0,vv.w,acc[0][3]);
            acc[1][0]=fmaf(p1,vv.x,acc[1][0]); acc[1][1]=fmaf(p1,vv.y,acc[1][1]); acc[1][2]=fmaf(p1,vv.z,acc[1][2]); acc[1][3]=fmaf(p1,vv.w,acc[1][3]);
            acc[2][0]=fmaf(p2,vv.x,acc[2][0]); acc[2][1]=fmaf(p2,vv.y,acc[2][1]); acc[2][2]=fmaf(p2,vv.z,acc[2][2]); acc[2][3]=fmaf(p2,vv.w,acc[2][3]);
            acc[3][0]=fmaf(p3,vv.x,acc[3][0]); acc[3][1]=fmaf(p3,vv.y,acc[3][1]); acc[3][2]=fmaf(p3,vv.z,acc[3][2]); acc[3][3]=fmaf(p3,vv.w,acc[3][3]);
        }
        __syncthreads();
    }
    #pragma unroll
    for (int i=0;i<4;i++){
        int gr = q0 + ty*4 + i;
        if (gr < LL){
            float inv = 1.0f/l_i[i];
            float4 o;
            o.x=acc[i][0]*inv; o.y=acc[i][1]*inv; o.z=acc[i][2]*inv; o.w=acc[i][3]*inv;
            *(float4*)(O + (size_t)(b*LL+gr)*DD + h*64 + tx*4) = o;
        }
    }
}

// ---------------- residual + LayerNorm (in place on hidden) ----------------
__global__ void k_addln(float* __restrict__ hid, const float* __restrict__ t,
                        const float* __restrict__ gg, const float* __restrict__ bbv){
    __shared__ float red[4];
    int r = blockIdx.x, tid = threadIdx.x;
    float4 a = *(float4*)(hid + (size_t)r*DD + tid*4);
    float4 c = *(const float4*)(t + (size_t)r*DD + tid*4);
    float x0=a.x+c.x, x1=a.y+c.y, x2=a.z+c.z, x3=a.w+c.w;
    float s = x0+x1+x2+x3;
    s = warp_red_sum(s);
    if ((tid&31)==0) red[tid>>5]=s;
    __syncthreads();
    float mean = (red[0]+red[1]+red[2]+red[3])*(1.f/512.f);
    float d0=x0-mean, d1=x1-mean, d2=x2-mean, d3=x3-mean;
    float q = d0*d0+d1*d1+d2*d2+d3*d3;
    q = warp_red_sum(q);
    __syncthreads();
    if ((tid&31)==0) red[tid>>5]=q;
    __syncthreads();
    float var = (red[0]+red[1]+red[2]+red[3])*(1.f/512.f);
    float inv = rsqrtf(var + 1e-12f);
    float4 gv = *(const float4*)(gg + tid*4);
    float4 bv = *(const float4*)(bbv + tid*4);
    float4 o;
    o.x = d0*inv*gv.x + bv.x;
    o.y = d1*inv*gv.y + bv.y;
    o.z = d2*inv*gv.z + bv.z;
    o.w = d3*inv*gv.w + bv.w;
    *(float4*)(hid + (size_t)r*DD + tid*4) = o;
}

// ---------------- host ----------------
extern "C" void kernel_launch(void* const* d_in, const int* in_sizes, int n_in,
                              void* d_out, int out_size) {
    const int*   input_ids = (const int*)  d_in[0];
    const int*   seq_lens  = (const int*)  d_in[1];
    const float* embed     = (const float*)d_in[2];
    const float* W_dec     = (const float*)d_in[3];
    const float* b_dec     = (const float*)d_in[4];
    const float* mem_W1    = (const float*)d_in[5];
    const float* mem_b1    = (const float*)d_in[6];
    const float* mem_W2    = (const float*)d_in[7];
    const float* mem_b2    = (const float*)d_in[8];
    const float* mem_ln_g  = (const float*)d_in[9];
    const float* mem_ln_b  = (const float*)d_in[10];
    const float* Wq = (const float*)d_in[11];
    const float* bq = (const float*)d_in[12];
    const float* Wk = (const float*)d_in[13];
    const float* bk = (const float*)d_in[14];
    const float* Wv = (const float*)d_in[15];
    const float* bv = (const float*)d_in[16];
    const float* Wo = (const float*)d_in[17];
    const float* bo = (const float*)d_in[18];
    const float* ln1_g = (const float*)d_in[19];
    const float* ln1_b = (const float*)d_in[20];
    const float* Wi = (const float*)d_in[21];
    const float* bi = (const float*)d_in[22];
    const float* Wf = (const float*)d_in[23];
    const float* bf = (const float*)d_in[24];
    const float* ln2_g = (const float*)d_in[25];
    const float* ln2_b = (const float*)d_in[26];

    float* hidden = (float*)d_out;

    float *p_q, *p_k, *p_v, *p_ctx, *p_t, *p_ff;
    cudaGetSymbolAddress((void**)&p_q,   g_q);
    cudaGetSymbolAddress((void**)&p_k,   g_k);
    cudaGetSymbolAddress((void**)&p_v,   g_v);
    cudaGetSymbolAddress((void**)&p_ctx, g_ctx);
    cudaGetSymbolAddress((void**)&p_t,   g_t);
    cudaGetSymbolAddress((void**)&p_ff,  g_ff);

    // topic memory
    k_wdec_softmax<<<TT, 256>>>(W_dec, b_dec);
    k_mem_gemm1<<<dim3(8, KSPLIT), 256>>>(mem_W1);
    k_mem_reduce<<<(TT*1024+255)/256, 256>>>(mem_b1);
    k_mem2_ln<<<TT, 256>>>(mem_W2, mem_b2, mem_ln_g, mem_ln_b);

    // build hidden into d_out
    k_build_hidden<<<BLROWS, 128>>>(input_ids, seq_lens, embed, hidden);

    const int MB = (BLROWS + 127)/128;  // 141
    for (int l = 0; l < NLAYER; l++) {
        const float* wq = Wq + (size_t)l*DD*DD;
        const float* wk = Wk + (size_t)l*DD*DD;
        const float* wv = Wv + (size_t)l*DD*DD;
        const float* wo = Wo + (size_t)l*DD*DD;
        const float* wi = Wi + (size_t)l*DD*FFDIM;
        const float* wf = Wf + (size_t)l*FFDIM*DD;

        k_gemm_mma<0><<<dim3(MB, DD/128), 256>>>(hidden, wq, bq + l*DD, p_q, BLROWS, DD, DD);
        k_gemm_mma<0><<<dim3(MB, DD/128), 256>>>(hidden, wk, bk + l*DD, p_k, BLROWS, DD, DD);
        k_gemm_mma<0><<<dim3(MB, DD/128), 256>>>(hidden, wv, bv + l*DD, p_v, BLROWS, DD, DD);

        k_attn<<<dim3((LL+63)/64, BB*HH), 256>>>(seq_lens, p_ctx);

        k_gemm_mma<0><<<dim3(MB, DD/128), 256>>>(p_ctx, wo, bo + l*DD, p_t, BLROWS, DD, DD);
        k_addln<<<BLROWS, 128>>>(hidden, p_t, ln1_g + l*DD, ln1_b + l*DD);

        k_gemm_mma<1><<<dim3(MB, FFDIM/128), 256>>>(hidden, wi, bi + l*FFDIM, p_ff, BLROWS, FFDIM, DD);
        k_gemm_mma<0><<<dim3(MB, DD/128), 256>>>(p_ff, wf, bf + l*DD, p_t, BLROWS, DD, FFDIM);
        k_addln<<<BLROWS, 128>>>(hidden, p_t, ln2_g + l*DD, ln2_b + l*DD);
    }
}

// round 3
// speedup vs baseline: 2.7335x; 1.3165x over previous
#include <cuda_runtime.h>
#include <cuda_bf16.h>
#include <math.h>

#define BB 32
#define SS 512
#define TT 50
#define LL 562      // S+T
#define DD 512
#define HH 8
#define FFDIM 2048
#define NLAYER 4
#define VBB 30000
#define BLROWS (BB*LL)   // 17984
#define KSPLIT 75
#define KCHUNK 400

// ---------------- scratch ----------------
__device__ float g_wd[TT*VBB];
__device__ float g_part[KSPLIT*TT*1024];
__device__ float g_hmem[TT*1024];
__device__ float g_topic[TT*DD];
__device__ float g_q[BLROWS*DD];
__device__ float g_k[BLROWS*DD];
__device__ float g_v[BLROWS*DD];
__device__ float g_ctx[BLROWS*DD];
__device__ float g_t[BLROWS*DD];
__device__ float g_ff[(size_t)BLROWS*FFDIM];

// ---------------- helpers ----------------
__device__ __forceinline__ float warp_red_sum(float v){
    #pragma unroll
    for (int o=16;o>0;o>>=1) v += __shfl_xor_sync(0xffffffffu, v, o);
    return v;
}
__device__ __forceinline__ float warp_red_max(float v){
    #pragma unroll
    for (int o=16;o>0;o>>=1) v = fmaxf(v, __shfl_xor_sync(0xffffffffu, v, o));
    return v;
}
__device__ __forceinline__ unsigned f2tf32(float x){
    unsigned r;
    asm("cvt.rna.tf32.f32 %0, %1;" : "=r"(r) : "f"(x));
    return r;
}
__device__ __forceinline__ void mma_tf32(float* d, const unsigned* a, unsigned b0, unsigned b1){
    asm volatile(
        "mma.sync.aligned.m16n8k8.row.col.f32.tf32.tf32.f32 "
        "{%0,%1,%2,%3}, {%4,%5,%6,%7}, {%8,%9}, {%0,%1,%2,%3};"
        : "+f"(d[0]), "+f"(d[1]), "+f"(d[2]), "+f"(d[3])
        : "r"(a[0]), "r"(a[1]), "r"(a[2]), "r"(a[3]), "r"(b0), "r"(b1));
}

// ---------------- topic memory pipeline ----------------
__global__ void k_wdec_softmax(const float* __restrict__ W, const float* __restrict__ bvec){
    int row = blockIdx.x, tid = threadIdx.x;
    __shared__ float red[32];
    const float* w = W + (size_t)row*VBB;
    float m = -1e30f;
    for (int i=tid;i<VBB;i+=1024) m = fmaxf(m, w[i]+bvec[i]);
    m = warp_red_max(m);
    if ((tid&31)==0) red[tid>>5]=m;
    __syncthreads();
    float mm = red[0];
    #pragma unroll
    for (int i=1;i<32;i++) mm = fmaxf(mm, red[i]);
    float s = 0.f;
    for (int i=tid;i<VBB;i+=1024) s += __expf(w[i]+bvec[i]-mm);
    s = warp_red_sum(s);
    __syncthreads();
    if ((tid&31)==0) red[tid>>5]=s;
    __syncthreads();
    float ss = 0.f;
    #pragma unroll
    for (int i=0;i<32;i++) ss += red[i];
    float inv = 1.0f/ss;
    for (int i=tid;i<VBB;i+=1024) g_wd[(size_t)row*VBB+i] = __expf(w[i]+bvec[i]-mm)*inv;
}

__global__ void k_mem_gemm1(const float* __restrict__ W1){
    __shared__ float wds[16][52];
    __shared__ float Ws[16][128];
    int n0 = blockIdx.x*128;
    int k0 = blockIdx.y*KCHUNK;
    int tid = threadIdx.x;
    int n = tid & 127, mb = (tid>>7)*25;
    float acc[25];
    #pragma unroll
    for (int i=0;i<25;i++) acc[i]=0.f;
    for (int kt=0; kt<KCHUNK; kt+=16){
        int kb = k0+kt;
        for (int x=tid;x<800;x+=256){ int m=x>>4, kk=x&15; wds[kk][m]=g_wd[(size_t)m*VBB + kb + kk]; }
        #pragma unroll
        for (int jj=0;jj<2;jj++){
            int idx = tid + jj*256;
            int r = idx>>5, c4 = (idx&31)*4;
            *(float4*)&Ws[r][c4] = *(const float4*)(W1 + (size_t)(kb+r)*1024 + n0 + c4);
        }
        __syncthreads();
        #pragma unroll
        for (int kk=0;kk<16;kk++){
            float w = Ws[kk][n];
            #pragma unroll
            for (int i=0;i<25;i++) acc[i] += wds[kk][mb+i]*w;
        }
        __syncthreads();
    }
    float* out = g_part + (size_t)blockIdx.y*(TT*1024);
    #pragma unroll
    for (int i=0;i<25;i++) out[(mb+i)*1024 + n0 + n] = acc[i];
}

__global__ void k_mem_reduce(const float* __restrict__ b1){
    int i = blockIdx.x*256 + threadIdx.x;
    if (i >= TT*1024) return;
    float s = 0.f;
    for (int ks=0; ks<KSPLIT; ks++) s += g_part[(size_t)ks*(TT*1024) + i];
    s += b1[i & 1023];
    g_hmem[i] = fmaxf(s, 0.f);
}

// one block of 512 threads per row: each thread one output col, then LN
__global__ __launch_bounds__(512)
void k_mem2_ln(const float* __restrict__ W2, const float* __restrict__ b2,
               const float* __restrict__ gg, const float* __restrict__ bbv){
    __shared__ float sh[1024];
    __shared__ float red[16];
    int row = blockIdx.x, tid = threadIdx.x;
    for (int i=tid;i<1024;i+=512) sh[i]=g_hmem[row*1024+i];
    __syncthreads();
    float a = 0.f;
    #pragma unroll 8
    for (int k=0;k<1024;k++) a = fmaf(sh[k], W2[(size_t)k*512+tid], a);
    a += b2[tid];
    float s = warp_red_sum(a);
    if ((tid&31)==0) red[tid>>5]=s;
    __syncthreads();
    float tot=0.f;
    #pragma unroll
    for (int i=0;i<16;i++) tot+=red[i];
    float mean = tot*(1.f/512.f);
    float d = a-mean;
    float q = warp_red_sum(d*d);
    __syncthreads();
    if ((tid&31)==0) red[tid>>5]=q;
    __syncthreads();
    float vq=0.f;
    #pragma unroll
    for (int i=0;i<16;i++) vq+=red[i];
    float inv = rsqrtf(vq*(1.f/512.f) + 1e-12f);
    g_topic[row*512+tid] = d*inv*gg[tid] + bbv[tid];
}

__global__ void k_build_hidden(const int* __restrict__ ids, const int* __restrict__ lens_p,
                               const float* __restrict__ embed, float* __restrict__ hid){
    int r = blockIdx.x;
    int b = r / LL, j = r % LL;
    int len = lens_p[b]; len = min(max(len,1),SS);
    const float* src;
    if (j >= len && j < len+TT){
        src = g_topic + (size_t)(j-len)*DD;
    } else {
        int sj = (j < len) ? j : (j - TT);
        sj = min(max(sj,0), SS-1);
        src = embed + (size_t)ids[b*SS + sj]*DD;
    }
    const float4* s4 = (const float4*)src;
    float4* dst = (float4*)(hid + (size_t)r*DD);
    dst[threadIdx.x] = s4[threadIdx.x];
}

// ---------------- TF32 tensor-core GEMM (register-prefetch pipelined) ----------------
template<int ACT>
__device__ __forceinline__
void gemm_body(const float* __restrict__ A, const float* __restrict__ W,
               const float* __restrict__ bias, float* __restrict__ C,
               int M, int N, int K, int m0, int n0)
{
    __shared__ float As[128][36];
    __shared__ float Ws[32][136];
    const int tid = threadIdx.x;
    const int lane = tid & 31, warp = tid >> 5;
    const int wm = warp >> 2, wn = warp & 3;
    const int q = lane & 3, g = lane >> 2;

    float acc[4][4][4];
    #pragma unroll
    for (int a=0;a<4;a++)
        #pragma unroll
        for (int b=0;b<4;b++)
            #pragma unroll
            for (int c=0;c<4;c++) acc[a][b][c]=0.f;

    float4 ra[4], rw[4];
    // prefetch tile 0
    #pragma unroll
    for (int i=0;i<4;i++){
        int s = tid + i*256;
        int m = s>>3, kv = s&7;
        int gr = m0+m;
        ra[i] = (gr<M) ? *(const float4*)(A + (size_t)gr*K + kv*4) : make_float4(0,0,0,0);
    }
    #pragma unroll
    for (int i=0;i<4;i++){
        int s = tid + i*256;
        int kk = s>>5, nv = s&31;
        rw[i] = *(const float4*)(W + (size_t)kk*N + n0 + nv*4);
    }

    const int nk = K >> 5;
    for (int kt = 0; kt < nk; kt++){
        // store prefetched tile with tf32 rounding
        #pragma unroll
        for (int i=0;i<4;i++){
            int s = tid + i*256;
            int m = s>>3, kv = s&7;
            uint4 t;
            t.x=f2tf32(ra[i].x); t.y=f2tf32(ra[i].y); t.z=f2tf32(ra[i].z); t.w=f2tf32(ra[i].w);
            *(uint4*)&As[m][kv*4] = t;
        }
        #pragma unroll
        for (int i=0;i<4;i++){
            int s = tid + i*256;
            int kk = s>>5, nv = s&31;
            uint4 t;
            t.x=f2tf32(rw[i].x); t.y=f2tf32(rw[i].y); t.z=f2tf32(rw[i].z); t.w=f2tf32(rw[i].w);
            *(uint4*)&Ws[kk][nv*4] = t;
        }
        __syncthreads();
        if (kt+1 < nk){
            int k0 = (kt+1)*32;
            #pragma unroll
            for (int i=0;i<4;i++){
                int s = tid + i*256;
                int m = s>>3, kv = s&7;
                int gr = m0+m;
                ra[i] = (gr<M) ? *(const float4*)(A + (size_t)gr*K + k0 + kv*4) : make_float4(0,0,0,0);
            }
            #pragma unroll
            for (int i=0;i<4;i++){
                int s = tid + i*256;
                int kk = s>>5, nv = s&31;
                rw[i] = *(const float4*)(W + (size_t)(k0+kk)*N + n0 + nv*4);
            }
        }
        #pragma unroll
        for (int k8=0;k8<32;k8+=8){
            unsigned af[4][4], bf[4][2];
            #pragma unroll
            for (int mi=0;mi<4;mi++){
                int mr = wm*64 + mi*16 + g;
                af[mi][0] = __float_as_uint(As[mr  ][k8+q  ]);
                af[mi][1] = __float_as_uint(As[mr+8][k8+q  ]);
                af[mi][2] = __float_as_uint(As[mr  ][k8+q+4]);
                af[mi][3] = __float_as_uint(As[mr+8][k8+q+4]);
            }
            #pragma unroll
            for (int nj=0;nj<4;nj++){
                int nc = wn*32 + nj*8 + g;
                bf[nj][0] = __float_as_uint(Ws[k8+q  ][nc]);
                bf[nj][1] = __float_as_uint(Ws[k8+q+4][nc]);
            }
            #pragma unroll
            for (int mi=0;mi<4;mi++)
                #pragma unroll
                for (int nj=0;nj<4;nj++)
                    mma_tf32(acc[mi][nj], af[mi], bf[nj][0], bf[nj][1]);
        }
        __syncthreads();
    }

    #pragma unroll
    for (int nj=0;nj<4;nj++){
        int c0 = n0 + wn*32 + nj*8 + q*2;
        float bv0 = bias[c0], bv1 = bias[c0+1];
        #pragma unroll
        for (int mi=0;mi<4;mi++){
            int r0 = m0 + wm*64 + mi*16 + g;
            float v0 = acc[mi][nj][0] + bv0;
            float v1 = acc[mi][nj][1] + bv1;
            float v2 = acc[mi][nj][2] + bv0;
            float v3 = acc[mi][nj][3] + bv1;
            if (ACT==1){
                v0 = 0.5f*v0*(1.0f+erff(v0*0.70710678118654752f));
                v1 = 0.5f*v1*(1.0f+erff(v1*0.70710678118654752f));
                v2 = 0.5f*v2*(1.0f+erff(v2*0.70710678118654752f));
                v3 = 0.5f*v3*(1.0f+erff(v3*0.70710678118654752f));
            }
            if (r0 < M)   { *(float2*)(C + (size_t)r0*N + c0) = make_float2(v0,v1); }
            if (r0+8 < M) { *(float2*)(C + (size_t)(r0+8)*N + c0) = make_float2(v2,v3); }
        }
    }
}

template<int ACT>
__global__ __launch_bounds__(256)
void k_gemm_mma(const float* __restrict__ A, const float* __restrict__ W,
                const float* __restrict__ bias, float* __restrict__ C,
                int M, int N, int K)
{
    gemm_body<ACT>(A, W, bias, C, M, N, K, blockIdx.x*128, blockIdx.y*128);
}

// fused Q/K/V projection: blockIdx.z selects weight/bias/output
__global__ __launch_bounds__(256)
void k_gemm_qkv(const float* __restrict__ A,
                const float* __restrict__ W0, const float* __restrict__ W1, const float* __restrict__ W2p,
                const float* __restrict__ b0, const float* __restrict__ b1, const float* __restrict__ b2p,
                float* __restrict__ o0, float* __restrict__ o1, float* __restrict__ o2)
{
    const float* W = (blockIdx.z==0) ? W0 : (blockIdx.z==1) ? W1 : W2p;
    const float* bs = (blockIdx.z==0) ? b0 : (blockIdx.z==1) ? b1 : b2p;
    float* C = (blockIdx.z==0) ? o0 : (blockIdx.z==1) ? o1 : o2;
    gemm_body<0>(A, W, bs, C, BLROWS, DD, DD, blockIdx.x*128, blockIdx.y*128);
}

// ---------------- tensor-core flash attention ----------------
// block 128 thr (4 warps), q-tile 64 (warp=16 rows), kv-tile 64, dh=64
__global__ __launch_bounds__(128)
void k_attn_mma(const int* __restrict__ lens_p, float* __restrict__ O){
    extern __shared__ float sm[];
    float (*Qs)[68] = (float(*)[68])sm;                       // 64x68
    float (*Ks)[68] = (float(*)[68])(sm + 64*68);             // 64x68
    float (*Vs)[72] = (float(*)[72])(sm + 2*64*68);           // 64x72
    float (*Ps)[68] = (float(*)[68])(sm + 2*64*68 + 64*72);   // 64x68
    int bh = blockIdx.y;
    int b = bh >> 3, h = bh & 7;
    int q0 = blockIdx.x*64;
    int tid = threadIdx.x, lane = tid&31, w = tid>>5;
    int g = lane>>2, q = lane&3;
    int len = lens_p[b]; len = min(max(len,1),SS);
    int valid = len + TT;
    const float* Qg = g_q + (size_t)b*LL*DD + h*64;
    const float* Kg = g_k + (size_t)b*LL*DD + h*64;
    const float* Vg = g_v + (size_t)b*LL*DD + h*64;

    // load Q tile (tf32)
    #pragma unroll
    for (int i=0;i<8;i++){
        int s = tid + i*128;
        int r = s>>4, c4 = (s&15)*4;
        int gr = q0+r;
        float4 v = (gr<LL) ? *(const float4*)(Qg + (size_t)gr*DD + c4) : make_float4(0,0,0,0);
        uint4 t; t.x=f2tf32(v.x); t.y=f2tf32(v.y); t.z=f2tf32(v.z); t.w=f2tf32(v.w);
        *(uint4*)&Qs[r][c4] = t;
    }
    __syncthreads();
    // Q fragments, register-resident for whole KV loop
    unsigned qf[8][4];
    {
        int mr = w*16 + g;
        #pragma unroll
        for (int kc=0;kc<8;kc++){
            qf[kc][0]=__float_as_uint(Qs[mr  ][kc*8+q  ]);
            qf[kc][1]=__float_as_uint(Qs[mr+8][kc*8+q  ]);
            qf[kc][2]=__float_as_uint(Qs[mr  ][kc*8+q+4]);
            qf[kc][3]=__float_as_uint(Qs[mr+8][kc*8+q+4]);
        }
    }
    float m0v=-1e30f, m1v=-1e30f, l0=0.f, l1=0.f;
    float oacc[8][4];
    #pragma unroll
    for (int nt=0;nt<8;nt++){ oacc[nt][0]=0.f;oacc[nt][1]=0.f;oacc[nt][2]=0.f;oacc[nt][3]=0.f; }

    const int nkt = (LL+63)/64;   // 9
    for (int kt=0; kt<nkt; kt++){
        int k0r = kt*64;
        #pragma unroll
        for (int i=0;i<8;i++){
            int s = tid + i*128;
            int r = s>>4, c4 = (s&15)*4;
            int gr = k0r+r;
            float4 kv4 = (gr<LL) ? *(const float4*)(Kg + (size_t)gr*DD + c4) : make_float4(0,0,0,0);
            float4 vv4 = (gr<LL) ? *(const float4*)(Vg + (size_t)gr*DD + c4) : make_float4(0,0,0,0);
            uint4 tk; tk.x=f2tf32(kv4.x); tk.y=f2tf32(kv4.y); tk.z=f2tf32(kv4.z); tk.w=f2tf32(kv4.w);
            uint4 tv; tv.x=f2tf32(vv4.x); tv.y=f2tf32(vv4.y); tv.z=f2tf32(vv4.z); tv.w=f2tf32(vv4.w);
            *(uint4*)&Ks[r][c4] = tk;
            *(uint4*)&Vs[r][c4] = tv;
        }
        __syncthreads();

        // S = Q @ K^T
        float sacc[8][4];
        #pragma unroll
        for (int nt=0;nt<8;nt++){ sacc[nt][0]=0.f;sacc[nt][1]=0.f;sacc[nt][2]=0.f;sacc[nt][3]=0.f; }
        #pragma unroll
        for (int kc=0;kc<8;kc++){
            #pragma unroll
            for (int nt=0;nt<8;nt++){
                unsigned b0 = __float_as_uint(Ks[nt*8+g][kc*8+q  ]);
                unsigned b1 = __float_as_uint(Ks[nt*8+g][kc*8+q+4]);
                mma_tf32(sacc[nt], qf[kc], b0, b1);
            }
        }
        // scale + mask + row stats
        float ml0=-1e30f, ml1=-1e30f;
        #pragma unroll
        for (int nt=0;nt<8;nt++){
            int c = k0r + nt*8 + 2*q;
            float msk0 = (c   >= valid) ? -10000.f : 0.f;
            float msk1 = (c+1 >= valid) ? -10000.f : 0.f;
            sacc[nt][0] = sacc[nt][0]*0.125f + msk0;
            sacc[nt][1] = sacc[nt][1]*0.125f + msk1;
            sacc[nt][2] = sacc[nt][2]*0.125f + msk0;
            sacc[nt][3] = sacc[nt][3]*0.125f + msk1;
            ml0 = fmaxf(ml0, fmaxf(sacc[nt][0], sacc[nt][1]));
            ml1 = fmaxf(ml1, fmaxf(sacc[nt][2], sacc[nt][3]));
        }
        ml0 = fmaxf(ml0, __shfl_xor_sync(0xffffffffu, ml0, 1));
        ml0 = fmaxf(ml0, __shfl_xor_sync(0xffffffffu, ml0, 2));
        ml1 = fmaxf(ml1, __shfl_xor_sync(0xffffffffu, ml1, 1));
        ml1 = fmaxf(ml1, __shfl_xor_sync(0xffffffffu, ml1, 2));
        float mn0 = fmaxf(m0v, ml0), mn1 = fmaxf(m1v, ml1);
        float al0 = __expf(m0v - mn0), al1 = __expf(m1v - mn1);
        m0v = mn0; m1v = mn1;
        float ps0 = 0.f, ps1 = 0.f;
        int mr = w*16 + g;
        #pragma unroll
        for (int nt=0;nt<8;nt++){
            float p0 = __expf(sacc[nt][0]-mn0);
            float p1 = __expf(sacc[nt][1]-mn0);
            float p2 = __expf(sacc[nt][2]-mn1);
            float p3 = __expf(sacc[nt][3]-mn1);
            ps0 += p0+p1; ps1 += p2+p3;
            int pc = nt*8 + 2*q;
            Ps[mr  ][pc]   = __uint_as_float(f2tf32(p0));
            Ps[mr  ][pc+1] = __uint_as_float(f2tf32(p1));
            Ps[mr+8][pc]   = __uint_as_float(f2tf32(p2));
            Ps[mr+8][pc+1] = __uint_as_float(f2tf32(p3));
        }
        ps0 += __shfl_xor_sync(0xffffffffu, ps0, 1);
        ps0 += __shfl_xor_sync(0xffffffffu, ps0, 2);
        ps1 += __shfl_xor_sync(0xffffffffu, ps1, 1);
        ps1 += __shfl_xor_sync(0xffffffffu, ps1, 2);
        l0 = l0*al0 + ps0;
        l1 = l1*al1 + ps1;
        #pragma unroll
        for (int nt=0;nt<8;nt++){
            oacc[nt][0]*=al0; oacc[nt][1]*=al0;
            oacc[nt][2]*=al1; oacc[nt][3]*=al1;
        }
        __syncwarp();
        // O += P @ V
        #pragma unroll
        for (int kc=0;kc<8;kc++){
            unsigned pf[4];
            pf[0]=__float_as_uint(Ps[mr  ][kc*8+q  ]);
            pf[1]=__float_as_uint(Ps[mr+8][kc*8+q  ]);
            pf[2]=__float_as_uint(Ps[mr  ][kc*8+q+4]);
            pf[3]=__float_as_uint(Ps[mr+8][kc*8+q+4]);
            #pragma unroll
            for (int nt=0;nt<8;nt++){
                unsigned b0 = __float_as_uint(Vs[kc*8+q  ][nt*8+g]);
                unsigned b1 = __float_as_uint(Vs[kc*8+q+4][nt*8+g]);
                mma_tf32(oacc[nt], pf, b0, b1);
            }
        }
        __syncthreads();
    }
    float inv0 = 1.f/l0, inv1 = 1.f/l1;
    int r0 = q0 + w*16 + g;
    float* Ob = O + (size_t)b*LL*DD + h*64;
    #pragma unroll
    for (int nt=0;nt<8;nt++){
        int c = nt*8 + 2*q;
        if (r0 < LL)   *(float2*)(Ob + (size_t)r0*DD + c)     = make_float2(oacc[nt][0]*inv0, oacc[nt][1]*inv0);
        if (r0+8 < LL) *(float2*)(Ob + (size_t)(r0+8)*DD + c) = make_float2(oacc[nt][2]*inv1, oacc[nt][3]*inv1);
    }
}

// ---------------- residual + LayerNorm ----------------
__global__ void k_addln(float* __restrict__ hid, const float* __restrict__ t,
                        const float* __restrict__ gg, const float* __restrict__ bbv){
    __shared__ float red[4];
    int r = blockIdx.x, tid = threadIdx.x;
    float4 a = *(float4*)(hid + (size_t)r*DD + tid*4);
    float4 c = *(const float4*)(t + (size_t)r*DD + tid*4);
    float x0=a.x+c.x, x1=a.y+c.y, x2=a.z+c.z, x3=a.w+c.w;
    float s = x0+x1+x2+x3;
    s = warp_red_sum(s);
    if ((tid&31)==0) red[tid>>5]=s;
    __syncthreads();
    float mean = (red[0]+red[1]+red[2]+red[3])*(1.f/512.f);
    float d0=x0-mean, d1=x1-mean, d2=x2-mean, d3=x3-mean;
    float q = d0*d0+d1*d1+d2*d2+d3*d3;
    q = warp_red_sum(q);
    __syncthreads();
    if ((tid&31)==0) red[tid>>5]=q;
    __syncthreads();
    float var = (red[0]+red[1]+red[2]+red[3])*(1.f/512.f);
    float inv = rsqrtf(var + 1e-12f);
    float4 gv = *(const float4*)(gg + tid*4);
    float4 bv = *(const float4*)(bbv + tid*4);
    float4 o;
    o.x = d0*inv*gv.x + bv.x;
    o.y = d1*inv*gv.y + bv.y;
    o.z = d2*inv*gv.z + bv.z;
    o.w = d3*inv*gv.w + bv.w;
    *(float4*)(hid + (size_t)r*DD + tid*4) = o;
}

// ---------------- host ----------------
extern "C" void kernel_launch(void* const* d_in, const int* in_sizes, int n_in,
                              void* d_out, int out_size) {
    const int*   input_ids = (const int*)  d_in[0];
    const int*   seq_lens  = (const int*)  d_in[1];
    const float* embed     = (const float*)d_in[2];
    const float* W_dec     = (const float*)d_in[3];
    const float* b_dec     = (const float*)d_in[4];
    const float* mem_W1    = (const float*)d_in[5];
    const float* mem_b1    = (const float*)d_in[6];
    const float* mem_W2    = (const float*)d_in[7];
    const float* mem_b2    = (const float*)d_in[8];
    const float* mem_ln_g  = (const float*)d_in[9];
    const float* mem_ln_b  = (const float*)d_in[10];
    const float* Wq = (const float*)d_in[11];
    const float* bq = (const float*)d_in[12];
    const float* Wk = (const float*)d_in[13];
    const float* bk = (const float*)d_in[14];
    const float* Wv = (const float*)d_in[15];
    const float* bv = (const float*)d_in[16];
    const float* Wo = (const float*)d_in[17];
    const float* bo = (const float*)d_in[18];
    const float* ln1_g = (const float*)d_in[19];
    const float* ln1_b = (const float*)d_in[20];
    const float* Wi = (const float*)d_in[21];
    const float* bi = (const float*)d_in[22];
    const float* Wf = (const float*)d_in[23];
    const float* bf = (const float*)d_in[24];
    const float* ln2_g = (const float*)d_in[25];
    const float* ln2_b = (const float*)d_in[26];

    float* hidden = (float*)d_out;

    float *p_q, *p_k, *p_v, *p_ctx, *p_t, *p_ff;
    cudaGetSymbolAddress((void**)&p_q,   g_q);
    cudaGetSymbolAddress((void**)&p_k,   g_k);
    cudaGetSymbolAddress((void**)&p_v,   g_v);
    cudaGetSymbolAddress((void**)&p_ctx, g_ctx);
    cudaGetSymbolAddress((void**)&p_t,   g_t);
    cudaGetSymbolAddress((void**)&p_ff,  g_ff);

    const int ATT_SMEM = (2*64*68 + 64*72 + 64*68)*4;   // 70656 B
    static int att_cfg = 0;
    if (!att_cfg){
        cudaFuncSetAttribute(k_attn_mma, cudaFuncAttributeMaxDynamicSharedMemorySize, ATT_SMEM);
        att_cfg = 1;
    }

    // topic memory
    k_wdec_softmax<<<TT, 1024>>>(W_dec, b_dec);
    k_mem_gemm1<<<dim3(8, KSPLIT), 256>>>(mem_W1);
    k_mem_reduce<<<(TT*1024+255)/256, 256>>>(mem_b1);
    k_mem2_ln<<<TT, 512>>>(mem_W2, mem_b2, mem_ln_g, mem_ln_b);

    // build hidden into d_out
    k_build_hidden<<<BLROWS, 128>>>(input_ids, seq_lens, embed, hidden);

    const int MB = (BLROWS + 127)/128;  // 141
    for (int l = 0; l < NLAYER; l++) {
        const float* wq = Wq + (size_t)l*DD*DD;
        const float* wk = Wk + (size_t)l*DD*DD;
        const float* wv = Wv + (size_t)l*DD*DD;
        const float* wo = Wo + (size_t)l*DD*DD;
        const float* wi = Wi + (size_t)l*DD*FFDIM;
        const float* wf = Wf + (size_t)l*FFDIM*DD;

        k_gemm_qkv<<<dim3(MB, DD/128, 3), 256>>>(hidden, wq, wk, wv,
                                                 bq + l*DD, bk + l*DD, bv + l*DD,
                                                 p_q, p_k, p_v);

        k_attn_mma<<<dim3((LL+63)/64, BB*HH), 128, ATT_SMEM>>>(seq_lens, p_ctx);

        k_gemm_mma<0><<<dim3(MB, DD/128), 256>>>(p_ctx, wo, bo + l*DD, p_t, BLROWS, DD, DD);
        k_addln<<<BLROWS, 128>>>(hidden, p_t, ln1_g + l*DD, ln1_b + l*DD);

        k_gemm_mma<1><<<dim3(MB, FFDIM/128), 256>>>(hidden, wi, bi + l*FFDIM, p_ff, BLROWS, FFDIM, DD);
        k_gemm_mma<0><<<dim3(MB, DD/128), 256>>>(p_ff, wf, bf + l*DD, p_t, BLROWS, DD, FFDIM);
        k_addln<<<BLROWS, 128>>>(hidden, p_t, ln2_g + l*DD, ln2_b + l*DD);
    }
}